// round 4
// baseline (speedup 1.0000x reference)
#include <cuda_runtime.h>

#define NT 16384
#define HD 1024
#define MD 512
#define NE 8

// Scratch (device globals — no allocation allowed)
__device__ int g_count[NE];
__device__ int g_perm[NE * NT];

__global__ void zero_counts_kernel() {
    if (threadIdx.x < NE) g_count[threadIdx.x] = 0;
}

// Router: each block = 32 tokens, 256 threads (8 warps).
// Each warp owns 4 tokens and, across its 32 lanes x 16 dims, the FULL 512
// hidden dims — so warp-reduced scores are exact (no fp atomics, deterministic).
__global__ __launch_bounds__(256) void routing_kernel(
    const float* __restrict__ X, const float* __restrict__ w1,
    const float* __restrict__ b1, const float* __restrict__ w2,
    const float* __restrict__ b2)
{
    __shared__ float sX[32][17];     // 32 tokens x 16 k
    __shared__ float sW[16][MD];     // 16 k x 512 m

    const int tid  = threadIdx.x;
    const int warp = tid >> 5;       // 0..7 -> token group
    const int lane = tid & 31;       // m base
    const int tokBase = blockIdx.x * 32;

    float acc[4][16];
    #pragma unroll
    for (int i = 0; i < 4; i++)
        #pragma unroll
        for (int j = 0; j < 16; j++) acc[i][j] = 0.f;

    for (int kc = 0; kc < HD; kc += 16) {
        // load X chunk: 32 x 16 floats = 128 float4 (threads 0..127)
        if (tid < 128) {
            int row = tid >> 2, v = tid & 3;
            float4 xv = *(const float4*)(X + (size_t)(tokBase + row) * HD + kc + v * 4);
            sX[row][v * 4 + 0] = xv.x;
            sX[row][v * 4 + 1] = xv.y;
            sX[row][v * 4 + 2] = xv.z;
            sX[row][v * 4 + 3] = xv.w;
        }
        // load w1 chunk: 16 x 512 floats = 2048 float4, 8 per thread
        #pragma unroll
        for (int it = 0; it < 8; it++) {
            int idx = tid + it * 256;     // 0..2047 float4s
            int row = idx >> 7;           // /128 -> 0..15
            int c4  = idx & 127;
            float4 wv = *(const float4*)(w1 + (size_t)(kc + row) * MD + c4 * 4);
            *((float4*)&sW[row][c4 * 4]) = wv;
        }
        __syncthreads();

        #pragma unroll
        for (int k = 0; k < 16; k++) {
            float xv[4];
            #pragma unroll
            for (int i = 0; i < 4; i++) xv[i] = sX[warp * 4 + i][k];
            #pragma unroll
            for (int j = 0; j < 16; j++) {
                float wv = sW[k][lane + 32 * j];
                #pragma unroll
                for (int i = 0; i < 4; i++) acc[i][j] = fmaf(xv[i], wv, acc[i][j]);
            }
        }
        __syncthreads();
    }

    // bias + relu + multiply by w2 -> partial scores per lane
    float ps[4][NE];
    #pragma unroll
    for (int i = 0; i < 4; i++)
        #pragma unroll
        for (int e = 0; e < NE; e++) ps[i][e] = 0.f;

    #pragma unroll
    for (int j = 0; j < 16; j++) {
        int m = lane + 32 * j;
        float bb = b1[m];
        #pragma unroll
        for (int i = 0; i < 4; i++) {
            float h = fmaxf(acc[i][j] + bb, 0.f);
            #pragma unroll
            for (int e = 0; e < NE; e++)
                ps[i][e] = fmaf(h, w2[m * NE + e], ps[i][e]);
        }
    }

    // full warp reduction (butterfly) -> all lanes hold the complete score
    #pragma unroll
    for (int i = 0; i < 4; i++)
        #pragma unroll
        for (int e = 0; e < NE; e++)
            #pragma unroll
            for (int off = 16; off > 0; off >>= 1)
                ps[i][e] += __shfl_xor_sync(0xffffffffu, ps[i][e], off);

    if (lane == 0) {
        #pragma unroll
        for (int i = 0; i < 4; i++) {
            int tok = tokBase + warp * 4 + i;
            int best = 0;
            float bs = ps[i][0] + b2[0];
            #pragma unroll
            for (int e = 1; e < NE; e++) {
                float s = ps[i][e] + b2[e];
                if (s > bs) { bs = s; best = e; }   // first-max tie-break, matches argmax
            }
            int slot = atomicAdd(&g_count[best], 1);
            g_perm[best * NT + slot] = tok;
        }
    }
}

// Expert GEMM: out[t,:] = X[t] @ W[e_t] + b[e_t], tokens gathered per expert.
// Tile: 64 tokens x 128 out dims, K chunk 16. 256 threads: 4 tok x 8 dims each.
__global__ __launch_bounds__(256) void expert_gemm_kernel(
    const float* __restrict__ X, const float* __restrict__ eW,
    const float* __restrict__ eB, float* __restrict__ out)
{
    const int e   = blockIdx.z;
    const int cnt = g_count[e];
    const int t0  = blockIdx.x * 64;
    if (t0 >= cnt) return;
    const int d0  = blockIdx.y * 128;

    __shared__ int   sTok[64];
    __shared__ float sX[64][17];
    __shared__ float sW[16][128];

    const int tid = threadIdx.x;
    const int tg  = tid >> 4;   // 0..15 -> tokens tg*4..tg*4+3
    const int dg  = tid & 15;   // dims dg + 16*j

    if (tid < 64) {
        int idx = t0 + tid;
        sTok[tid] = (idx < cnt) ? g_perm[e * NT + idx] : g_perm[e * NT + t0];
    }
    __syncthreads();

    float acc[4][8];
    #pragma unroll
    for (int i = 0; i < 4; i++)
        #pragma unroll
        for (int j = 0; j < 8; j++) acc[i][j] = 0.f;

    const float* W = eW + (size_t)e * HD * HD;

    for (int kc = 0; kc < HD; kc += 16) {
        // gather X chunk: 64 rows x 16 floats = 256 float4 (1 per thread)
        {
            int row = tid >> 2, v = tid & 3;
            float4 xv = *(const float4*)(X + (size_t)sTok[row] * HD + kc + v * 4);
            sX[row][v * 4 + 0] = xv.x;
            sX[row][v * 4 + 1] = xv.y;
            sX[row][v * 4 + 2] = xv.z;
            sX[row][v * 4 + 3] = xv.w;
        }
        // W chunk: 16 x 128 floats = 512 float4, 2 per thread (coalesced)
        #pragma unroll
        for (int it = 0; it < 2; it++) {
            int idx = tid + it * 256;   // 0..511
            int row = idx >> 5;         // 0..15
            int c4  = idx & 31;
            float4 wv = *(const float4*)(W + (size_t)(kc + row) * HD + d0 + c4 * 4);
            *((float4*)&sW[row][c4 * 4]) = wv;
        }
        __syncthreads();

        #pragma unroll
        for (int k = 0; k < 16; k++) {
            float xv[4];
            #pragma unroll
            for (int i = 0; i < 4; i++) xv[i] = sX[tg * 4 + i][k];
            #pragma unroll
            for (int j = 0; j < 8; j++) {
                float wv = sW[k][dg + 16 * j];
                #pragma unroll
                for (int i = 0; i < 4; i++) acc[i][j] = fmaf(xv[i], wv, acc[i][j]);
            }
        }
        __syncthreads();
    }

    #pragma unroll
    for (int i = 0; i < 4; i++) {
        int ti = t0 + tg * 4 + i;
        if (ti >= cnt) continue;
        int tok = sTok[tg * 4 + i];
        float* orow = out + (size_t)tok * HD;
        #pragma unroll
        for (int j = 0; j < 8; j++) {
            int d = d0 + dg + 16 * j;
            orow[d] = acc[i][j] + eB[e * HD + d];
        }
    }
}

extern "C" void kernel_launch(void* const* d_in, const int* in_sizes, int n_in,
                              void* d_out, int out_size)
{
    const float* X  = (const float*)d_in[0];   // hidden_states [4,4096,1024]
    const float* w1 = (const float*)d_in[1];   // [1024,512]
    const float* b1 = (const float*)d_in[2];   // [512]
    const float* w2 = (const float*)d_in[3];   // [512,8]
    const float* b2 = (const float*)d_in[4];   // [8]
    const float* eW = (const float*)d_in[5];   // [8,1024,1024]
    const float* eB = (const float*)d_in[6];   // [8,1024]
    float* out = (float*)d_out;                // [4,4096,1024]

    zero_counts_kernel<<<1, 32>>>();
    routing_kernel<<<NT / 32, 256>>>(X, w1, b1, w2, b2);
    expert_gemm_kernel<<<dim3(NT / 64, HD / 128, NE), 256>>>(X, eW, eB, out);
}

// round 6
// speedup vs baseline: 2.4987x; 2.4987x over previous
#include <cuda_runtime.h>
#include <cuda_bf16.h>
#include <cstdint>

#define NT 16384
#define HD 1024
#define MD 512
#define NE 8

// ---------------- device scratch (no runtime allocation allowed) ----------------
__device__ int g_count[NE];
__device__ int g_perm[NE * NT];
__device__ __nv_bfloat16 g_Xhi[(size_t)NT * HD];
__device__ __nv_bfloat16 g_Xlo[(size_t)NT * HD];
__device__ __nv_bfloat16 g_Wthi[(size_t)NE * HD * HD];  // [e][d][k] (transposed)
__device__ __nv_bfloat16 g_Wtlo[(size_t)NE * HD * HD];

// ---------------- PTX helpers (compute_103-safe: no tcgen05) ----------------
__device__ __forceinline__ uint32_t smem_to_u32(const void* p) {
    uint32_t a;
    asm("{ .reg .u64 t; cvta.to.shared.u64 t, %1; cvt.u32.u64 %0, t; }" : "=r"(a) : "l"(p));
    return a;
}
#define CP_ASYNC16(dst, src) \
    asm volatile("cp.async.cg.shared.global [%0], [%1], 16;" :: "r"(dst), "l"(src))
#define CP_COMMIT() asm volatile("cp.async.commit_group;" ::: "memory")
#define CP_WAIT(n)  asm volatile("cp.async.wait_group %0;" :: "n"(n) : "memory")

__device__ __forceinline__ void ldmatrix_x4(uint32_t& r0, uint32_t& r1, uint32_t& r2,
                                            uint32_t& r3, uint32_t addr) {
    asm volatile("ldmatrix.sync.aligned.m8n8.x4.shared.b16 {%0, %1, %2, %3}, [%4];"
                 : "=r"(r0), "=r"(r1), "=r"(r2), "=r"(r3) : "r"(addr));
}
__device__ __forceinline__ void mma_bf16(float* d, const uint32_t* a, const uint32_t* b) {
    asm volatile(
        "mma.sync.aligned.m16n8k16.row.col.f32.bf16.bf16.f32 "
        "{%0, %1, %2, %3}, {%4, %5, %6, %7}, {%8, %9}, {%0, %1, %2, %3};"
        : "+f"(d[0]), "+f"(d[1]), "+f"(d[2]), "+f"(d[3])
        : "r"(a[0]), "r"(a[1]), "r"(a[2]), "r"(a[3]), "r"(b[0]), "r"(b[1]));
}

// ---------------- prep kernels ----------------
__global__ void zero_counts_kernel() {
    if (threadIdx.x < NE) g_count[threadIdx.x] = 0;
}

__global__ __launch_bounds__(256) void split_X_kernel(const float* __restrict__ X) {
    size_t i = ((size_t)blockIdx.x * 256 + threadIdx.x) * 4;
    float4 x = *(const float4*)(X + i);
    float v[4] = {x.x, x.y, x.z, x.w};
    #pragma unroll
    for (int j = 0; j < 4; j++) {
        __nv_bfloat16 hi = __float2bfloat16(v[j]);
        __nv_bfloat16 lo = __float2bfloat16(v[j] - __bfloat162float(hi));
        g_Xhi[i + j] = hi;
        g_Xlo[i + j] = lo;
    }
}

// Wt[e][d][k] = W[e][k][d], split into hi/lo bf16. 32x32 smem-tiled transpose.
__global__ __launch_bounds__(256) void transpose_split_W_kernel(const float* __restrict__ eW) {
    __shared__ float tile[32][33];
    const int e  = blockIdx.z;
    const int k0 = blockIdx.x * 32;
    const int d0 = blockIdx.y * 32;
    const int tx = threadIdx.x, ty = threadIdx.y;   // 32 x 8
    const float* W = eW + (size_t)e * HD * HD;
    #pragma unroll
    for (int r = 0; r < 32; r += 8)
        tile[ty + r][tx] = W[(size_t)(k0 + ty + r) * HD + d0 + tx];
    __syncthreads();
    #pragma unroll
    for (int r = 0; r < 32; r += 8) {
        float v = tile[tx][ty + r];
        __nv_bfloat16 hi = __float2bfloat16(v);
        __nv_bfloat16 lo = __float2bfloat16(v - __bfloat162float(hi));
        size_t o = (size_t)e * HD * HD + (size_t)(d0 + ty + r) * HD + k0 + tx;
        g_Wthi[o] = hi;
        g_Wtlo[o] = lo;
    }
}

// ---------------- router (exact fp32 — argmax must match the fp32 reference) ----------------
__global__ __launch_bounds__(256) void routing_kernel(
    const float* __restrict__ X, const float* __restrict__ w1,
    const float* __restrict__ b1, const float* __restrict__ w2,
    const float* __restrict__ b2)
{
    __shared__ float sX[32][17];
    __shared__ float sW[16][MD];

    const int tid  = threadIdx.x;
    const int warp = tid >> 5;
    const int lane = tid & 31;
    const int tokBase = blockIdx.x * 32;

    float acc[4][16];
    #pragma unroll
    for (int i = 0; i < 4; i++)
        #pragma unroll
        for (int j = 0; j < 16; j++) acc[i][j] = 0.f;

    for (int kc = 0; kc < HD; kc += 16) {
        if (tid < 128) {
            int row = tid >> 2, v = tid & 3;
            float4 xv = *(const float4*)(X + (size_t)(tokBase + row) * HD + kc + v * 4);
            sX[row][v * 4 + 0] = xv.x;
            sX[row][v * 4 + 1] = xv.y;
            sX[row][v * 4 + 2] = xv.z;
            sX[row][v * 4 + 3] = xv.w;
        }
        #pragma unroll
        for (int it = 0; it < 8; it++) {
            int idx = tid + it * 256;
            int row = idx >> 7;
            int c4  = idx & 127;
            float4 wv = *(const float4*)(w1 + (size_t)(kc + row) * MD + c4 * 4);
            *((float4*)&sW[row][c4 * 4]) = wv;
        }
        __syncthreads();

        #pragma unroll
        for (int k = 0; k < 16; k++) {
            float xv[4];
            #pragma unroll
            for (int i = 0; i < 4; i++) xv[i] = sX[warp * 4 + i][k];
            #pragma unroll
            for (int j = 0; j < 16; j++) {
                float wv = sW[k][lane + 32 * j];
                #pragma unroll
                for (int i = 0; i < 4; i++) acc[i][j] = fmaf(xv[i], wv, acc[i][j]);
            }
        }
        __syncthreads();
    }

    float ps[4][NE];
    #pragma unroll
    for (int i = 0; i < 4; i++)
        #pragma unroll
        for (int e = 0; e < NE; e++) ps[i][e] = 0.f;

    #pragma unroll
    for (int j = 0; j < 16; j++) {
        int m = lane + 32 * j;
        float bb = b1[m];
        #pragma unroll
        for (int i = 0; i < 4; i++) {
            float h = fmaxf(acc[i][j] + bb, 0.f);
            #pragma unroll
            for (int e = 0; e < NE; e++)
                ps[i][e] = fmaf(h, w2[m * NE + e], ps[i][e]);
        }
    }

    #pragma unroll
    for (int i = 0; i < 4; i++)
        #pragma unroll
        for (int e = 0; e < NE; e++)
            #pragma unroll
            for (int off = 16; off > 0; off >>= 1)
                ps[i][e] += __shfl_xor_sync(0xffffffffu, ps[i][e], off);

    if (lane == 0) {
        #pragma unroll
        for (int i = 0; i < 4; i++) {
            int tok = tokBase + warp * 4 + i;
            int best = 0;
            float bs = ps[i][0] + b2[0];
            #pragma unroll
            for (int e = 1; e < NE; e++) {
                float s = ps[i][e] + b2[e];
                if (s > bs) { bs = s; best = e; }
            }
            int slot = atomicAdd(&g_count[best], 1);
            g_perm[best * NT + slot] = tok;
        }
    }
}

// ---------------- expert GEMM via mma.sync bf16 (hi@hi + hi@lo + lo@hi) ----------------
// Block tile M=128 tokens x N=256 dims, 256 threads = 8 warps (2m x 4n), warp tile 64x64.
// K staged in chunks of 64 bf16, double-buffered via cp.async. 48 chunks (3 passes x 16).
// Smem rows padded to 72 elems (144B) -> ldmatrix & cp.async conflict-free.

#define ROWB     144                       // bytes per padded smem row (64 bf16 + 8 pad)
#define A_BYTES  (128 * ROWB)              // 18432
#define B_BYTES  (256 * ROWB)              // 36864
#define STAGE_BYTES (A_BYTES + B_BYTES)    // 55296
#define OFF_TOK  (2 * STAGE_BYTES)         // 110592
#define SMEM_TOTAL_EXP (OFF_TOK + 512)
#define NCHUNK   48

__global__ __launch_bounds__(256, 1)
void expert_mma_kernel(const float* __restrict__ eB, float* __restrict__ out)
{
    const int e   = blockIdx.z;
    const int cnt = g_count[e];
    const int t0  = blockIdx.x * 128;
    if (t0 >= cnt) return;
    const int d0  = blockIdx.y * 256;

    extern __shared__ __align__(128) char smem[];
    const uint32_t sb = smem_to_u32(smem);
    const int tid   = threadIdx.x;
    const int lane  = tid & 31;
    const int wid   = tid >> 5;
    const int warpM = wid >> 2;        // 0..1 -> m offset 64*warpM
    const int warpN = wid & 3;         // 0..3 -> n offset 64*warpN

    int* sTok = (int*)(smem + OFF_TOK);
    if (tid < 128) {
        int idx = t0 + tid;
        sTok[tid] = g_perm[e * NT + (idx < cnt ? idx : cnt - 1)];
    }
    __syncthreads();

    const size_t eoff = (size_t)e * HD * HD;
    const __nv_bfloat16* Apass[3] = {g_Xhi, g_Xhi, g_Xlo};
    const __nv_bfloat16* Bpass[3] = {g_Wthi + eoff, g_Wtlo + eoff, g_Wthi + eoff};

    // ---- stage loader: A = 128 gathered token rows x 64, B = 256 W^T rows x 64 ----
    auto load_stage = [&](int stage, int chunk) {
        const int pass = chunk >> 4;
        const int k0   = (chunk & 15) << 6;
        const __nv_bfloat16* As = Apass[pass];
        const __nv_bfloat16* Bs = Bpass[pass];
        const uint32_t sA = sb + stage * STAGE_BYTES;
        const uint32_t sB = sA + A_BYTES;
        #pragma unroll
        for (int it = 0; it < 4; it++) {           // A: 1024 x 16B
            int idx = tid + it * 256;
            int row = idx >> 3, seg = idx & 7;
            CP_ASYNC16(sA + row * ROWB + seg * 16,
                       As + (size_t)sTok[row] * HD + k0 + seg * 8);
        }
        #pragma unroll
        for (int it = 0; it < 8; it++) {           // B: 2048 x 16B
            int idx = tid + it * 256;
            int row = idx >> 3, seg = idx & 7;
            CP_ASYNC16(sB + row * ROWB + seg * 16,
                       Bs + (size_t)(d0 + row) * HD + k0 + seg * 8);
        }
        CP_COMMIT();
    };

    float acc[4][8][4];
    #pragma unroll
    for (int i = 0; i < 4; i++)
        #pragma unroll
        for (int j = 0; j < 8; j++)
            #pragma unroll
            for (int q = 0; q < 4; q++) acc[i][j][q] = 0.f;

    // per-thread ldmatrix base offsets (within a stage)
    const uint32_t aBase = (uint32_t)((warpM * 64 + (lane & 15)) * ROWB + (lane >> 4) * 16);
    const uint32_t bBase = (uint32_t)((warpN * 64 + ((lane >> 4) & 1) * 8 + (lane & 7)) * ROWB
                                      + ((lane >> 3) & 1) * 16);

    load_stage(0, 0);

    for (int c = 0; c < NCHUNK; c++) {
        const int s = c & 1;
        if (c + 1 < NCHUNK) { load_stage(s ^ 1, c + 1); CP_WAIT(1); }
        else                { CP_WAIT(0); }
        __syncthreads();

        const uint32_t sA = sb + s * STAGE_BYTES;
        const uint32_t sB = sA + A_BYTES;
        #pragma unroll
        for (int kk = 0; kk < 4; kk++) {
            uint32_t a[4][4];
            #pragma unroll
            for (int i = 0; i < 4; i++)
                ldmatrix_x4(a[i][0], a[i][1], a[i][2], a[i][3],
                            sA + aBase + i * 16 * ROWB + kk * 32);
            uint32_t b[8][2];
            #pragma unroll
            for (int j2 = 0; j2 < 4; j2++)
                ldmatrix_x4(b[2 * j2][0], b[2 * j2][1], b[2 * j2 + 1][0], b[2 * j2 + 1][1],
                            sB + bBase + j2 * 16 * ROWB + kk * 32);
            #pragma unroll
            for (int i = 0; i < 4; i++)
                #pragma unroll
                for (int j = 0; j < 8; j++)
                    mma_bf16(acc[i][j], a[i], b[j]);
        }
        __syncthreads();
    }

    // ---- epilogue: acc -> out with bias ----
    const int qr = lane >> 2;          // 0..7
    const int qc = (lane & 3) * 2;     // 0,2,4,6
    #pragma unroll
    for (int i = 0; i < 4; i++) {
        const int r0 = warpM * 64 + i * 16 + qr;
        #pragma unroll
        for (int half = 0; half < 2; half++) {
            const int row = r0 + half * 8;
            if (t0 + row >= cnt) continue;
            float* orow = out + (size_t)sTok[row] * HD + d0;
            #pragma unroll
            for (int j = 0; j < 8; j++) {
                const int n = warpN * 64 + j * 8 + qc;
                float2 bb = *(const float2*)(eB + e * HD + d0 + n);
                float2 v;
                v.x = acc[i][j][half * 2 + 0] + bb.x;
                v.y = acc[i][j][half * 2 + 1] + bb.y;
                *(float2*)(orow + n) = v;
            }
        }
    }
}

// ---------------- host ----------------
extern "C" void kernel_launch(void* const* d_in, const int* in_sizes, int n_in,
                              void* d_out, int out_size)
{
    const float* X  = (const float*)d_in[0];   // [4,4096,1024]
    const float* w1 = (const float*)d_in[1];   // [1024,512]
    const float* b1 = (const float*)d_in[2];   // [512]
    const float* w2 = (const float*)d_in[3];   // [512,8]
    const float* b2 = (const float*)d_in[4];   // [8]
    const float* eW = (const float*)d_in[5];   // [8,1024,1024]
    const float* eB = (const float*)d_in[6];   // [8,1024]
    float* out = (float*)d_out;                // [4,4096,1024]

    static bool attr_set = false;
    if (!attr_set) {
        cudaFuncSetAttribute(expert_mma_kernel,
                             cudaFuncAttributeMaxDynamicSharedMemorySize, SMEM_TOTAL_EXP);
        attr_set = true;
    }

    zero_counts_kernel<<<1, 32>>>();
    split_X_kernel<<<(NT * HD) / (256 * 4), 256>>>(X);
    transpose_split_W_kernel<<<dim3(HD / 32, HD / 32, NE), dim3(32, 8)>>>(eW);
    routing_kernel<<<NT / 32, 256>>>(X, w1, b1, w2, b2);
    expert_mma_kernel<<<dim3(NT / 128, HD / 256, NE), 256, SMEM_TOTAL_EXP>>>(eB, out);
}

// round 7
// speedup vs baseline: 3.3671x; 1.3475x over previous
#include <cuda_runtime.h>
#include <cuda_bf16.h>
#include <cstdint>

#define NT 16384
#define HD 1024
#define MD 512
#define NE 8

// ---------------- device scratch (no runtime allocation allowed) ----------------
__device__ int g_count[NE];
__device__ int g_perm[NE * NT];
__device__ int g_nflag;
__device__ int g_flag[NT];
__device__ float g_h[(size_t)NT * MD];                  // router hidden (approx, fp32)
__device__ __nv_bfloat16 g_Xhi[(size_t)NT * HD];
__device__ __nv_bfloat16 g_Xlo[(size_t)NT * HD];
__device__ __nv_bfloat16 g_W1t1[(size_t)MD * HD];       // w1^T split hi  [m][k]
__device__ __nv_bfloat16 g_W1t2[(size_t)MD * HD];       // w1^T split lo
__device__ __nv_bfloat16 g_Wthi[(size_t)NE * HD * HD];  // expert W^T hi [e][d][k]
__device__ __nv_bfloat16 g_Wtlo[(size_t)NE * HD * HD];

// ---------------- PTX helpers (compute_103-safe: no tcgen05) ----------------
__device__ __forceinline__ uint32_t smem_to_u32(const void* p) {
    uint32_t a;
    asm("{ .reg .u64 t; cvta.to.shared.u64 t, %1; cvt.u32.u64 %0, t; }" : "=r"(a) : "l"(p));
    return a;
}
#define CP_ASYNC16(dst, src) \
    asm volatile("cp.async.cg.shared.global [%0], [%1], 16;" :: "r"(dst), "l"(src))
#define CP_COMMIT() asm volatile("cp.async.commit_group;" ::: "memory")
#define CP_WAIT(n)  asm volatile("cp.async.wait_group %0;" :: "n"(n) : "memory")

__device__ __forceinline__ void ldmatrix_x4(uint32_t& r0, uint32_t& r1, uint32_t& r2,
                                            uint32_t& r3, uint32_t addr) {
    asm volatile("ldmatrix.sync.aligned.m8n8.x4.shared.b16 {%0, %1, %2, %3}, [%4];"
                 : "=r"(r0), "=r"(r1), "=r"(r2), "=r"(r3) : "r"(addr));
}
__device__ __forceinline__ void mma_bf16(float* d, const uint32_t* a, const uint32_t* b) {
    asm volatile(
        "mma.sync.aligned.m16n8k16.row.col.f32.bf16.bf16.f32 "
        "{%0, %1, %2, %3}, {%4, %5, %6, %7}, {%8, %9}, {%0, %1, %2, %3};"
        : "+f"(d[0]), "+f"(d[1]), "+f"(d[2]), "+f"(d[3])
        : "r"(a[0]), "r"(a[1]), "r"(a[2]), "r"(a[3]), "r"(b[0]), "r"(b[1]));
}

// ---------------- prep kernels ----------------
__global__ void zero_counts_kernel() {
    if (threadIdx.x < NE) g_count[threadIdx.x] = 0;
    if (threadIdx.x == NE) g_nflag = 0;
}

__global__ __launch_bounds__(256) void split_X_kernel(const float* __restrict__ X) {
    size_t i = ((size_t)blockIdx.x * 256 + threadIdx.x) * 4;
    float4 x = *(const float4*)(X + i);
    float v[4] = {x.x, x.y, x.z, x.w};
    #pragma unroll
    for (int j = 0; j < 4; j++) {
        __nv_bfloat16 hi = __float2bfloat16(v[j]);
        __nv_bfloat16 lo = __float2bfloat16(v[j] - __bfloat162float(hi));
        g_Xhi[i + j] = hi;
        g_Xlo[i + j] = lo;
    }
}

// w1 [k=1024][m=512] -> w1^T [m][k], split hi/lo bf16.
__global__ __launch_bounds__(256) void transpose_split_w1_kernel(const float* __restrict__ w1) {
    __shared__ float tile[32][33];
    const int k0 = blockIdx.x * 32;
    const int m0 = blockIdx.y * 32;
    const int tx = threadIdx.x, ty = threadIdx.y;   // 32 x 8
    #pragma unroll
    for (int r = 0; r < 32; r += 8)
        tile[ty + r][tx] = w1[(size_t)(k0 + ty + r) * MD + m0 + tx];
    __syncthreads();
    #pragma unroll
    for (int r = 0; r < 32; r += 8) {
        float v = tile[tx][ty + r];
        __nv_bfloat16 hi = __float2bfloat16(v);
        __nv_bfloat16 lo = __float2bfloat16(v - __bfloat162float(hi));
        size_t o = (size_t)(m0 + ty + r) * HD + k0 + tx;
        g_W1t1[o] = hi;
        g_W1t2[o] = lo;
    }
}

// Wt[e][d][k] = W[e][k][d], split into hi/lo bf16.
__global__ __launch_bounds__(256) void transpose_split_W_kernel(const float* __restrict__ eW) {
    __shared__ float tile[32][33];
    const int e  = blockIdx.z;
    const int k0 = blockIdx.x * 32;
    const int d0 = blockIdx.y * 32;
    const int tx = threadIdx.x, ty = threadIdx.y;   // 32 x 8
    const float* W = eW + (size_t)e * HD * HD;
    #pragma unroll
    for (int r = 0; r < 32; r += 8)
        tile[ty + r][tx] = W[(size_t)(k0 + ty + r) * HD + d0 + tx];
    __syncthreads();
    #pragma unroll
    for (int r = 0; r < 32; r += 8) {
        float v = tile[tx][ty + r];
        __nv_bfloat16 hi = __float2bfloat16(v);
        __nv_bfloat16 lo = __float2bfloat16(v - __bfloat162float(hi));
        size_t o = (size_t)e * HD * HD + (size_t)(d0 + ty + r) * HD + k0 + tx;
        g_Wthi[o] = hi;
        g_Wtlo[o] = lo;
    }
}

// ---------------- shared HMMA tile config ----------------
#define ROWB     144
#define A_BYTES  (128 * ROWB)
#define B_BYTES  (256 * ROWB)
#define STAGE_BYTES (A_BYTES + B_BYTES)
#define OFF_TOK  (2 * STAGE_BYTES)
#define SMEM_TOTAL_EXP (OFF_TOK + 512)
#define NCHUNK   48

// ---------------- router GEMM1 via HMMA (x1w1 + x1w2 + x2w1) ----------------
// Tile M=128 tokens x N=256 hidden dims; writes h = relu(acc + b1) fp32 to g_h.
__global__ __launch_bounds__(256, 1)
void gemm1_mma_kernel(const float* __restrict__ b1)
{
    const int t0 = blockIdx.x * 128;
    const int d0 = blockIdx.y * 256;

    extern __shared__ __align__(128) char smem[];
    const uint32_t sb = smem_to_u32(smem);
    const int tid   = threadIdx.x;
    const int lane  = tid & 31;
    const int wid   = tid >> 5;
    const int warpM = wid >> 2;
    const int warpN = wid & 3;

    const __nv_bfloat16* Apass[3] = {g_Xhi, g_Xhi, g_Xlo};
    const __nv_bfloat16* Bpass[3] = {g_W1t1, g_W1t2, g_W1t1};

    auto load_stage = [&](int stage, int chunk) {
        const int pass = chunk >> 4;
        const int k0   = (chunk & 15) << 6;
        const __nv_bfloat16* As = Apass[pass];
        const __nv_bfloat16* Bs = Bpass[pass];
        const uint32_t sA = sb + stage * STAGE_BYTES;
        const uint32_t sB = sA + A_BYTES;
        #pragma unroll
        for (int it = 0; it < 4; it++) {
            int idx = tid + it * 256;
            int row = idx >> 3, seg = idx & 7;
            CP_ASYNC16(sA + row * ROWB + seg * 16,
                       As + (size_t)(t0 + row) * HD + k0 + seg * 8);
        }
        #pragma unroll
        for (int it = 0; it < 8; it++) {
            int idx = tid + it * 256;
            int row = idx >> 3, seg = idx & 7;
            CP_ASYNC16(sB + row * ROWB + seg * 16,
                       Bs + (size_t)(d0 + row) * HD + k0 + seg * 8);
        }
        CP_COMMIT();
    };

    float acc[4][8][4];
    #pragma unroll
    for (int i = 0; i < 4; i++)
        #pragma unroll
        for (int j = 0; j < 8; j++)
            #pragma unroll
            for (int q = 0; q < 4; q++) acc[i][j][q] = 0.f;

    const uint32_t aBase = (uint32_t)((warpM * 64 + (lane & 15)) * ROWB + (lane >> 4) * 16);
    const uint32_t bBase = (uint32_t)((warpN * 64 + ((lane >> 4) & 1) * 8 + (lane & 7)) * ROWB
                                      + ((lane >> 3) & 1) * 16);

    load_stage(0, 0);

    for (int c = 0; c < NCHUNK; c++) {
        const int s = c & 1;
        if (c + 1 < NCHUNK) { load_stage(s ^ 1, c + 1); CP_WAIT(1); }
        else                { CP_WAIT(0); }
        __syncthreads();

        const uint32_t sA = sb + s * STAGE_BYTES;
        const uint32_t sB = sA + A_BYTES;
        #pragma unroll
        for (int kk = 0; kk < 4; kk++) {
            uint32_t a[4][4];
            #pragma unroll
            for (int i = 0; i < 4; i++)
                ldmatrix_x4(a[i][0], a[i][1], a[i][2], a[i][3],
                            sA + aBase + i * 16 * ROWB + kk * 32);
            uint32_t b[8][2];
            #pragma unroll
            for (int j2 = 0; j2 < 4; j2++)
                ldmatrix_x4(b[2 * j2][0], b[2 * j2][1], b[2 * j2 + 1][0], b[2 * j2 + 1][1],
                            sB + bBase + j2 * 16 * ROWB + kk * 32);
            #pragma unroll
            for (int i = 0; i < 4; i++)
                #pragma unroll
                for (int j = 0; j < 8; j++)
                    mma_bf16(acc[i][j], a[i], b[j]);
        }
        __syncthreads();
    }

    const int qr = lane >> 2;
    const int qc = (lane & 3) * 2;
    #pragma unroll
    for (int i = 0; i < 4; i++) {
        const int r0 = warpM * 64 + i * 16 + qr;
        #pragma unroll
        for (int half = 0; half < 2; half++) {
            const int row = r0 + half * 8;
            float* hrow = g_h + (size_t)(t0 + row) * MD + d0;
            #pragma unroll
            for (int j = 0; j < 8; j++) {
                const int n = warpN * 64 + j * 8 + qc;
                float2 bb = *(const float2*)(b1 + d0 + n);
                float2 v;
                v.x = fmaxf(acc[i][j][half * 2 + 0] + bb.x, 0.f);
                v.y = fmaxf(acc[i][j][half * 2 + 1] + bb.y, 0.f);
                *(float2*)(hrow + n) = v;
            }
        }
    }
}

// ---------------- score + margin-checked routing ----------------
#define MARGIN_TH 2e-3f

__global__ __launch_bounds__(256) void score_kernel(
    const float* __restrict__ w2, const float* __restrict__ b2)
{
    __shared__ float sW2[MD * 9];   // padded rows of 9 -> conflict-free
    const int tid  = threadIdx.x;
    const int warp = tid >> 5;
    const int lane = tid & 31;

    for (int i = tid; i < MD; i += 256) {
        #pragma unroll
        for (int e = 0; e < NE; e++) sW2[i * 9 + e] = w2[i * NE + e];
    }
    __syncthreads();

    const int tok = blockIdx.x * 8 + warp;
    const float* hrow = g_h + (size_t)tok * MD;

    float ps[NE];
    #pragma unroll
    for (int e = 0; e < NE; e++) ps[e] = 0.f;
    #pragma unroll
    for (int j = 0; j < 16; j++) {
        const int m = lane + 32 * j;
        const float h = hrow[m];
        #pragma unroll
        for (int e = 0; e < NE; e++) ps[e] = fmaf(h, sW2[m * 9 + e], ps[e]);
    }
    #pragma unroll
    for (int e = 0; e < NE; e++)
        #pragma unroll
        for (int off = 16; off > 0; off >>= 1)
            ps[e] += __shfl_xor_sync(0xffffffffu, ps[e], off);

    if (lane == 0) {
        float s[NE];
        #pragma unroll
        for (int e = 0; e < NE; e++) s[e] = ps[e] + b2[e];
        int best = 0;
        float b1v = s[0], b2v = -1e30f;
        #pragma unroll
        for (int e = 1; e < NE; e++) {
            if (s[e] > b1v) { b2v = b1v; b1v = s[e]; best = e; }
            else if (s[e] > b2v) b2v = s[e];
        }
        if (b1v - b2v > MARGIN_TH) {
            int slot = atomicAdd(&g_count[best], 1);
            g_perm[best * NT + slot] = tok;
        } else {
            int f = atomicAdd(&g_nflag, 1);
            g_flag[f] = tok;
        }
    }
}

// Exact fp32 recompute for flagged (close-call) tokens. Grid-strided over flags.
__global__ __launch_bounds__(256) void fixup_kernel(
    const float* __restrict__ X, const float* __restrict__ w1,
    const float* __restrict__ b1, const float* __restrict__ w2,
    const float* __restrict__ b2)
{
    __shared__ float sX[HD];
    __shared__ float sred[256 / 32][NE];
    const int tid  = threadIdx.x;
    const int warp = tid >> 5;
    const int lane = tid & 31;
    const int nf = g_nflag;

    for (int i = blockIdx.x; i < nf; i += gridDim.x) {
        const int tok = g_flag[i];
        __syncthreads();
        for (int k = tid; k < HD; k += 256)
            sX[k] = X[(size_t)tok * HD + k];
        __syncthreads();

        // thread handles m = tid and m = tid+256 (coalesced w1 reads)
        float a0 = 0.f, a1 = 0.f;
        for (int k = 0; k < HD; k++) {
            const float xv = sX[k];
            a0 = fmaf(xv, w1[(size_t)k * MD + tid], a0);
            a1 = fmaf(xv, w1[(size_t)k * MD + tid + 256], a1);
        }
        const float h0 = fmaxf(a0 + b1[tid], 0.f);
        const float h1 = fmaxf(a1 + b1[tid + 256], 0.f);

        float ps[NE];
        #pragma unroll
        for (int e = 0; e < NE; e++)
            ps[e] = h0 * w2[tid * NE + e] + h1 * w2[(tid + 256) * NE + e];
        #pragma unroll
        for (int e = 0; e < NE; e++)
            #pragma unroll
            for (int off = 16; off > 0; off >>= 1)
                ps[e] += __shfl_xor_sync(0xffffffffu, ps[e], off);
        if (lane == 0) {
            #pragma unroll
            for (int e = 0; e < NE; e++) sred[warp][e] = ps[e];
        }
        __syncthreads();
        if (tid == 0) {
            float s[NE];
            #pragma unroll
            for (int e = 0; e < NE; e++) {
                float v = b2[e];
                #pragma unroll
                for (int w = 0; w < 8; w++) v += sred[w][e];
                s[e] = v;
            }
            int best = 0;
            float bs = s[0];
            #pragma unroll
            for (int e = 1; e < NE; e++)
                if (s[e] > bs) { bs = s[e]; best = e; }
            int slot = atomicAdd(&g_count[best], 1);
            g_perm[best * NT + slot] = tok;
        }
    }
}

// ---------------- expert GEMM via mma.sync bf16 (hi@hi + hi@lo + lo@hi) ----------------
__global__ __launch_bounds__(256, 1)
void expert_mma_kernel(const float* __restrict__ eB, float* __restrict__ out)
{
    const int e   = blockIdx.z;
    const int cnt = g_count[e];
    const int t0  = blockIdx.x * 128;
    if (t0 >= cnt) return;
    const int d0  = blockIdx.y * 256;

    extern __shared__ __align__(128) char smem[];
    const uint32_t sb = smem_to_u32(smem);
    const int tid   = threadIdx.x;
    const int lane  = tid & 31;
    const int wid   = tid >> 5;
    const int warpM = wid >> 2;
    const int warpN = wid & 3;

    int* sTok = (int*)(smem + OFF_TOK);
    if (tid < 128) {
        int idx = t0 + tid;
        sTok[tid] = g_perm[e * NT + (idx < cnt ? idx : cnt - 1)];
    }
    __syncthreads();

    const size_t eoff = (size_t)e * HD * HD;
    const __nv_bfloat16* Apass[3] = {g_Xhi, g_Xhi, g_Xlo};
    const __nv_bfloat16* Bpass[3] = {g_Wthi + eoff, g_Wtlo + eoff, g_Wthi + eoff};

    auto load_stage = [&](int stage, int chunk) {
        const int pass = chunk >> 4;
        const int k0   = (chunk & 15) << 6;
        const __nv_bfloat16* As = Apass[pass];
        const __nv_bfloat16* Bs = Bpass[pass];
        const uint32_t sA = sb + stage * STAGE_BYTES;
        const uint32_t sB = sA + A_BYTES;
        #pragma unroll
        for (int it = 0; it < 4; it++) {
            int idx = tid + it * 256;
            int row = idx >> 3, seg = idx & 7;
            CP_ASYNC16(sA + row * ROWB + seg * 16,
                       As + (size_t)sTok[row] * HD + k0 + seg * 8);
        }
        #pragma unroll
        for (int it = 0; it < 8; it++) {
            int idx = tid + it * 256;
            int row = idx >> 3, seg = idx & 7;
            CP_ASYNC16(sB + row * ROWB + seg * 16,
                       Bs + (size_t)(d0 + row) * HD + k0 + seg * 8);
        }
        CP_COMMIT();
    };

    float acc[4][8][4];
    #pragma unroll
    for (int i = 0; i < 4; i++)
        #pragma unroll
        for (int j = 0; j < 8; j++)
            #pragma unroll
            for (int q = 0; q < 4; q++) acc[i][j][q] = 0.f;

    const uint32_t aBase = (uint32_t)((warpM * 64 + (lane & 15)) * ROWB + (lane >> 4) * 16);
    const uint32_t bBase = (uint32_t)((warpN * 64 + ((lane >> 4) & 1) * 8 + (lane & 7)) * ROWB
                                      + ((lane >> 3) & 1) * 16);

    load_stage(0, 0);

    for (int c = 0; c < NCHUNK; c++) {
        const int s = c & 1;
        if (c + 1 < NCHUNK) { load_stage(s ^ 1, c + 1); CP_WAIT(1); }
        else                { CP_WAIT(0); }
        __syncthreads();

        const uint32_t sA = sb + s * STAGE_BYTES;
        const uint32_t sB = sA + A_BYTES;
        #pragma unroll
        for (int kk = 0; kk < 4; kk++) {
            uint32_t a[4][4];
            #pragma unroll
            for (int i = 0; i < 4; i++)
                ldmatrix_x4(a[i][0], a[i][1], a[i][2], a[i][3],
                            sA + aBase + i * 16 * ROWB + kk * 32);
            uint32_t b[8][2];
            #pragma unroll
            for (int j2 = 0; j2 < 4; j2++)
                ldmatrix_x4(b[2 * j2][0], b[2 * j2][1], b[2 * j2 + 1][0], b[2 * j2 + 1][1],
                            sB + bBase + j2 * 16 * ROWB + kk * 32);
            #pragma unroll
            for (int i = 0; i < 4; i++)
                #pragma unroll
                for (int j = 0; j < 8; j++)
                    mma_bf16(acc[i][j], a[i], b[j]);
        }
        __syncthreads();
    }

    const int qr = lane >> 2;
    const int qc = (lane & 3) * 2;
    #pragma unroll
    for (int i = 0; i < 4; i++) {
        const int r0 = warpM * 64 + i * 16 + qr;
        #pragma unroll
        for (int half = 0; half < 2; half++) {
            const int row = r0 + half * 8;
            if (t0 + row >= cnt) continue;
            float* orow = out + (size_t)sTok[row] * HD + d0;
            #pragma unroll
            for (int j = 0; j < 8; j++) {
                const int n = warpN * 64 + j * 8 + qc;
                float2 bb = *(const float2*)(eB + e * HD + d0 + n);
                float2 v;
                v.x = acc[i][j][half * 2 + 0] + bb.x;
                v.y = acc[i][j][half * 2 + 1] + bb.y;
                *(float2*)(orow + n) = v;
            }
        }
    }
}

// ---------------- host ----------------
extern "C" void kernel_launch(void* const* d_in, const int* in_sizes, int n_in,
                              void* d_out, int out_size)
{
    const float* X  = (const float*)d_in[0];
    const float* w1 = (const float*)d_in[1];
    const float* b1 = (const float*)d_in[2];
    const float* w2 = (const float*)d_in[3];
    const float* b2 = (const float*)d_in[4];
    const float* eW = (const float*)d_in[5];
    const float* eB = (const float*)d_in[6];
    float* out = (float*)d_out;

    static bool attr_set = false;
    if (!attr_set) {
        cudaFuncSetAttribute(expert_mma_kernel,
                             cudaFuncAttributeMaxDynamicSharedMemorySize, SMEM_TOTAL_EXP);
        cudaFuncSetAttribute(gemm1_mma_kernel,
                             cudaFuncAttributeMaxDynamicSharedMemorySize, SMEM_TOTAL_EXP);
        attr_set = true;
    }

    zero_counts_kernel<<<1, 32>>>();
    split_X_kernel<<<(NT * HD) / (256 * 4), 256>>>(X);
    transpose_split_w1_kernel<<<dim3(HD / 32, MD / 32), dim3(32, 8)>>>(w1);
    transpose_split_W_kernel<<<dim3(HD / 32, HD / 32, NE), dim3(32, 8)>>>(eW);
    gemm1_mma_kernel<<<dim3(NT / 128, MD / 256), 256, SMEM_TOTAL_EXP>>>(b1);
    score_kernel<<<NT / 8, 256>>>(w2, b2);
    fixup_kernel<<<64, 256>>>(X, w1, b1, w2, b2);
    expert_mma_kernel<<<dim3(NT / 128, HD / 256, NE), 256, SMEM_TOTAL_EXP>>>(eB, out);
}